// round 15
// baseline (speedup 1.0000x reference)
#include <cuda_runtime.h>
#include <cstdint>

// Problem dims (fixed by reference setup_inputs)
#define TB 4      // batch
#define TT 512    // tokens
#define TD 1024   // d_model
#define TNC 16    // n_concepts
#define TH 256    // init_size
#define NBATCH (TB * TNC)   // 64 batched GEMMs

// ---------------- scratch (__device__ globals; allocation-free rule) ----------------
// Packed operand buffers: uint2 = {bf16x2 hi, bf16x2 lo} for one k-adjacent fp32 pair.
__device__ uint2 g_xA  [(size_t)TB * TT * (TD / 2)];        // x, k-pairs along d  (GEMM1 A)
__device__ uint2 g_xB  [(size_t)TB * (TT / 2) * TD];        // x, k-pairs along t  (GEMM3 B)
__device__ uint2 g_wB  [(size_t)TNC * (TD / 2) * TH];       // w_qs, k-pairs along d (GEMM1 B)
__device__ uint2 g_wqP [(size_t)NBATCH * TT * (TH / 2)];    // wq, k-pairs along h (GEMM2 A+B)
__device__ uint2 g_attnP[(size_t)NBATCH * TT * (TT / 2)];   // attn, k-pairs along t (GEMM3 A)
__device__ float g_attn_fb[(size_t)NBATCH * TT * TT];       // fp32 attn if d_out has no slot

// ---------------- helpers ----------------
__device__ __forceinline__ uint32_t smem_u32(const void* p) {
    uint32_t a;
    asm("{ .reg .u64 t; cvta.to.shared.u64 t, %1; cvt.u32.u64 %0, t; }" : "=r"(a) : "l"(p));
    return a;
}
__device__ __forceinline__ void cp16(uint32_t dst, const void* src) {
    asm volatile("cp.async.cg.shared.global [%0], [%1], 16;" :: "r"(dst), "l"(src) : "memory");
}
__device__ __forceinline__ void cp_commit() { asm volatile("cp.async.commit_group;" ::: "memory"); }
__device__ __forceinline__ void cp_wait0()  { asm volatile("cp.async.wait_group 0;" ::: "memory"); }

// bf16 hi/lo split of a k-adjacent fp32 pair -> {hi word, lo word} (lo half = even k)
__device__ __forceinline__ uint2 bf16_split2(float f0, float f1) {
    uint32_t h, l;
    asm("cvt.rn.bf16x2.f32 %0, %1, %2;" : "=r"(h) : "f"(f1), "f"(f0));
    const float h0 = __uint_as_float(h << 16);
    const float h1 = __uint_as_float(h & 0xFFFF0000u);
    const float l0 = f0 - h0;
    const float l1 = f1 - h1;
    asm("cvt.rn.bf16x2.f32 %0, %1, %2;" : "=r"(l) : "f"(l1), "f"(l0));
    return make_uint2(h, l);
}
__device__ __forceinline__ void mma_bf16(float* d, const uint32_t* a, const uint32_t* b) {
    asm volatile(
        "mma.sync.aligned.m16n8k16.row.col.f32.bf16.bf16.f32 "
        "{%0,%1,%2,%3}, {%4,%5,%6,%7}, {%8,%9}, {%0,%1,%2,%3};"
        : "+f"(d[0]), "+f"(d[1]), "+f"(d[2]), "+f"(d[3])
        : "r"(a[0]), "r"(a[1]), "r"(a[2]), "r"(a[3]), "r"(b[0]), "r"(b[1]));
}

// ---------------- prep kernels: fp32 -> packed {hi,lo} ----------------
__global__ __launch_bounds__(256) void k_prep_xA(const float* __restrict__ x,
                                                 uint2* __restrict__ xA) {
    const size_t i = (size_t)blockIdx.x * 256 + threadIdx.x;   // 1M pairs along d
    const float2 v = reinterpret_cast<const float2*>(x)[i];
    xA[i] = bf16_split2(v.x, v.y);
}
__global__ __launch_bounds__(256) void k_prep_xB(const float* __restrict__ x,
                                                 uint2* __restrict__ xB) {
    const size_t i = (size_t)blockIdx.x * 256 + threadIdx.x;   // 1M: (b, t2, d)
    const size_t d = i & (TD - 1), bt2 = i >> 10;
    const size_t b = bt2 >> 8, t2 = bt2 & 255;
    const float* p = x + (b * TT + 2 * t2) * TD + d;
    xB[i] = bf16_split2(p[0], p[TD]);
}
__global__ __launch_bounds__(256) void k_prep_wB(const float* __restrict__ w,
                                                 uint2* __restrict__ wB) {
    const size_t i = (size_t)blockIdx.x * 256 + threadIdx.x;   // 2M: (n, d2, h)
    const size_t h = i & (TH - 1), nd2 = i >> 8;
    const size_t n = nd2 >> 9, d2 = nd2 & 511;
    const float* p = w + (n * TD + 2 * d2) * TH + h;
    wB[i] = bf16_split2(p[0], p[TH]);
}

// ---------------- packed bf16x3 batched GEMM: C tile 128x128 ----------------
// MODE 1: wq = x @ w_qs   (K=1024) A=g_xA,  B=g_wB direct  -> packed g_wqP
// MODE 2: logits = wq@wq^T (K=256) A=g_wqP, B=g_wqP BTR    -> fp32 Cout
// MODE 3: e = attn @ x     (K=512) A=g_attnP, B=g_xB direct-> fp32 Cout
// SMEM (uint2): sA[2][128][12] (banks 12*lr+lq: conflict-free), sB direct [2][8][132]
// (banks 4*lq+lr), BTR [2][128][12]. MODE2 total = exactly 49152 B.
template <int MODE>
__global__ __launch_bounds__(256, 2) void k_gemm_pk(const uint2* __restrict__ Apk,
                                                    const uint2* __restrict__ Bpk,
                                                    float* __restrict__ Cout,
                                                    uint2* __restrict__ CoutPk) {
    constexpr int K2   = (MODE == 1) ? 512 : (MODE == 2) ? 128 : 256;  // K/2 pairs
    constexpr int NKB  = K2 / 8;
    constexpr int LDA2 = K2;
    constexpr int LDB2 = (MODE == 1) ? TH : (MODE == 2) ? 128 : TD;
    constexpr int LDC  = (MODE == 2) ? TT : TD;
    constexpr bool BTR = (MODE == 2);
    constexpr int BRR  = BTR ? 128 : 8;
    constexpr int BCC  = BTR ? 12  : 132;

    __shared__ uint2 sA[2][128][12];
    __shared__ uint2 sB[2][BRR][BCC];

    const int tid = threadIdx.x, wid = tid >> 5, lane = tid & 31;
    const int wm = wid & 1, wn = wid >> 1;     // 2x4 warp grid, warp tile 64x32
    const int lr = lane >> 2, lq = lane & 3;
    const int z = blockIdx.z;
    const int m0 = blockIdx.y * 128;
    const int n0 = blockIdx.x * 128;

    size_t aoff, boff;
    if constexpr (MODE == 1) {
        aoff = (size_t)(z >> 4) * TT * 512;          // xA batch b
        boff = (size_t)(z & 15) * 512 * TH;          // wB concept n
    } else if constexpr (MODE == 2) {
        aoff = (size_t)z * TT * 128;                 // wqP
        boff = aoff;
    } else {
        aoff = (size_t)z * TT * 256;                 // attnP
        boff = (size_t)(z >> 4) * 256 * TD;          // xB batch b
    }
    const uint2* pA = Apk + aoff + (size_t)m0 * LDA2;
    const uint2* pB = BTR ? (Bpk + boff + (size_t)n0 * LDB2)
                          : (Bpk + boff + n0);

    float acc[4][4][4];
#pragma unroll
    for (int mi = 0; mi < 4; mi++)
#pragma unroll
        for (int ni = 0; ni < 4; ni++)
#pragma unroll
            for (int e = 0; e < 4; e++) acc[mi][ni][e] = 0.0f;

    // ---- cp.async staging: one 8-pair (16-K) block per stage ----
    auto issue_stage = [&](int kb, int s) {
#pragma unroll
        for (int i = 0; i < 2; i++) {
            const int cid = tid + i * 256;
            const int ar = cid >> 2, ac4 = cid & 3;
            cp16(smem_u32(&sA[s][ar][ac4 * 2]),
                 pA + (size_t)ar * LDA2 + kb * 8 + ac4 * 2);
            if constexpr (BTR) {
                const int nr = cid >> 2, kc4 = cid & 3;
                cp16(smem_u32(&sB[s][nr][kc4 * 2]),
                     pB + (size_t)nr * LDB2 + kb * 8 + kc4 * 2);
            } else {
                const int kr = cid >> 6, nc = cid & 63;
                cp16(smem_u32(&sB[s][kr][nc * 2]),
                     pB + (size_t)(kb * 8 + kr) * LDB2 + nc * 2);
            }
        }
        cp_commit();
    };

    issue_stage(0, 0);

#pragma unroll 1
    for (int kb = 0; kb < NKB; kb++) {
        const int s = kb & 1;
        cp_wait0();
        __syncthreads();
        if (kb + 1 < NKB) issue_stage(kb + 1, s ^ 1);   // copy overlaps MMAs below

        // ---- fragment loads: one LDS.64 per {hi,lo} register pair; NO split math ----
        uint32_t ah[4][4], al[4][4], bh[4][2], bl[4][2];
#pragma unroll
        for (int mi = 0; mi < 4; mi++) {
            const int row = wm * 64 + mi * 16 + lr;
            const uint2 a0 = sA[s][row][lq];
            const uint2 a1 = sA[s][row + 8][lq];
            const uint2 a2 = sA[s][row][lq + 4];
            const uint2 a3 = sA[s][row + 8][lq + 4];
            ah[mi][0] = a0.x; al[mi][0] = a0.y;
            ah[mi][1] = a1.x; al[mi][1] = a1.y;
            ah[mi][2] = a2.x; al[mi][2] = a2.y;
            ah[mi][3] = a3.x; al[mi][3] = a3.y;
        }
#pragma unroll
        for (int ni = 0; ni < 4; ni++) {
            const int n = wn * 32 + ni * 8 + lr;
            uint2 b0, b1;
            if constexpr (BTR) { b0 = sB[s][n][lq]; b1 = sB[s][n][lq + 4]; }
            else               { b0 = sB[s][lq][n]; b1 = sB[s][lq + 4][n]; }
            bh[ni][0] = b0.x; bl[ni][0] = b0.y;
            bh[ni][1] = b1.x; bl[ni][1] = b1.y;
        }

        // pass-major MMA ordering: dependent acc updates are 16 MMAs apart
#pragma unroll
        for (int mi = 0; mi < 4; mi++)
#pragma unroll
            for (int ni = 0; ni < 4; ni++)
                mma_bf16(acc[mi][ni], ah[mi], bh[ni]);   // hi*hi
#pragma unroll
        for (int mi = 0; mi < 4; mi++)
#pragma unroll
            for (int ni = 0; ni < 4; ni++)
                mma_bf16(acc[mi][ni], ah[mi], bl[ni]);   // hi*lo
#pragma unroll
        for (int mi = 0; mi < 4; mi++)
#pragma unroll
            for (int ni = 0; ni < 4; ni++)
                mma_bf16(acc[mi][ni], al[mi], bh[ni]);   // lo*hi
    }

    // ---- epilogue ----
    const int rbase = m0 + wm * 64 + lr;
    const int cbase = n0 + wn * 32 + lq * 2;
#pragma unroll
    for (int mi = 0; mi < 4; mi++)
#pragma unroll
        for (int ni = 0; ni < 4; ni++)
#pragma unroll
            for (int h = 0; h < 2; h++) {
                const int row = rbase + mi * 16 + h * 8;
                const int col = cbase + ni * 8;
                const float v0 = acc[mi][ni][2 * h];
                const float v1 = acc[mi][ni][2 * h + 1];
                if constexpr (MODE == 1) {
                    // packed wq: k-pairs along h (adjacent cols) — same values the
                    // R14 path produced by store-fp32-then-split
                    CoutPk[(size_t)z * TT * 128 + (size_t)row * 128 + col / 2] =
                        bf16_split2(v0, v1);
                } else {
                    float* dst = Cout + (size_t)z * TT * LDC + (size_t)row * LDC + col;
                    *reinterpret_cast<float2*>(dst) = make_float2(v0, v1);
                }
            }
}

// ---------------- softmax over rows of 512 + packed attn emit ----------------
__global__ __launch_bounds__(256) void k_softmax(float* __restrict__ attn,
                                                 uint2* __restrict__ attnP) {
    __shared__ float redm[8];
    __shared__ float reds[8];
    const size_t row = blockIdx.x;
    float2* p = reinterpret_cast<float2*>(attn + row * TT);
    const int tid = threadIdx.x;

    const float2 v = p[tid];          // adjacent t pair = the GEMM3 k-pair
    float m = fmaxf(v.x, v.y);
#pragma unroll
    for (int o = 16; o; o >>= 1) m = fmaxf(m, __shfl_xor_sync(0xffffffffu, m, o));
    if ((tid & 31) == 0) redm[tid >> 5] = m;
    __syncthreads();
    float mAll = redm[0];
#pragma unroll
    for (int w = 1; w < 8; w++) mAll = fmaxf(mAll, redm[w]);

    const float e0 = expf(v.x - mAll);
    const float e1 = expf(v.y - mAll);
    float s = e0 + e1;
#pragma unroll
    for (int o = 16; o; o >>= 1) s += __shfl_xor_sync(0xffffffffu, s, o);
    if ((tid & 31) == 0) reds[tid >> 5] = s;
    __syncthreads();
    float sAll = 0.0f;
#pragma unroll
    for (int w = 0; w < 8; w++) sAll += reds[w];
    const float inv = 1.0f / sAll;
    const float a0 = e0 * inv, a1 = e1 * inv;
    p[tid] = make_float2(a0, a1);
    attnP[row * 256 + tid] = bf16_split2(a0, a1);
}

// ---------------- launcher ----------------
extern "C" void kernel_launch(void* const* d_in, const int* in_sizes, int n_in,
                              void* d_out, int out_size) {
    (void)in_sizes; (void)n_in;
    const float* x   = (const float*)d_in[0];
    const float* wqs = (const float*)d_in[1];
    // d_in[2] = w_ks: unused in reference math (faithful to source bug)
    float* out = (float*)d_out;

    const long long EAGG = (long long)NBATCH * TT * TD;  // 33,554,432
    const long long ATTN = (long long)NBATCH * TT * TT;  // 16,777,216

    float* attn;
    if ((long long)out_size >= EAGG + ATTN) {
        attn = out + EAGG;
    } else {
        void* p = nullptr;
        cudaGetSymbolAddress(&p, g_attn_fb);
        attn = (float*)p;
    }
    void *pxA, *pxB, *pwB, *pwqP, *pattnP;
    cudaGetSymbolAddress(&pxA, g_xA);
    cudaGetSymbolAddress(&pxB, g_xB);
    cudaGetSymbolAddress(&pwB, g_wB);
    cudaGetSymbolAddress(&pwqP, g_wqP);
    cudaGetSymbolAddress(&pattnP, g_attnP);
    uint2* xA = (uint2*)pxA;
    uint2* xB = (uint2*)pxB;
    uint2* wB = (uint2*)pwB;
    uint2* wqP = (uint2*)pwqP;
    uint2* attnP = (uint2*)pattnP;

    // prep: pack inputs into {hi,lo} pairs (once per element)
    k_prep_xA<<<(TB * TT * TD / 2) / 256, 256>>>(x, xA);
    k_prep_xB<<<(TB * TT * TD / 2) / 256, 256>>>(x, xB);
    k_prep_wB<<<(TNC * TD * TH / 2) / 256, 256>>>(wqs, wB);

    // GEMM1: wq = x @ w_qs -> packed wqP
    k_gemm_pk<1><<<dim3(TH / 128, TT / 128, NBATCH), 256>>>(xA, wB, nullptr, wqP);
    // GEMM2: logits = wq @ wq^T -> fp32 attn
    k_gemm_pk<2><<<dim3(TT / 128, TT / 128, NBATCH), 256>>>(wqP, wqP, attn, nullptr);
    // softmax (+ packed attn emit)
    k_softmax<<<NBATCH * TT, 256>>>(attn, attnP);
    // GEMM3: e = attn @ x -> fp32 out
    k_gemm_pk<3><<<dim3(TD / 128, TT / 128, NBATCH), 256>>>(attnP, xB, out, nullptr);
}

// round 16
// speedup vs baseline: 1.4275x; 1.4275x over previous
#include <cuda_runtime.h>
#include <cstdint>

// Problem dims (fixed by reference setup_inputs)
#define TB 4      // batch
#define TT 512    // tokens
#define TD 1024   // d_model
#define TNC 16    // n_concepts
#define TH 256    // init_size
#define NBATCH (TB * TNC)   // 64 batched GEMMs

// ---------------- scratch (__device__ globals; allocation-free rule) ----------------
__device__ float g_wq[(size_t)NBATCH * TT * TH];      // fp32 wq[z][t][h]
__device__ float g_attn_fb[(size_t)NBATCH * TT * TT]; // fp32 attn if d_out has no slot

// ---------------- helpers ----------------
__device__ __forceinline__ uint32_t smem_u32(const void* p) {
    uint32_t a;
    asm("{ .reg .u64 t; cvta.to.shared.u64 t, %1; cvt.u32.u64 %0, t; }" : "=r"(a) : "l"(p));
    return a;
}
__device__ __forceinline__ void cp16(uint32_t dst, const void* src) {
    asm volatile("cp.async.cg.shared.global [%0], [%1], 16;" :: "r"(dst), "l"(src) : "memory");
}
__device__ __forceinline__ void cp_commit() { asm volatile("cp.async.commit_group;" ::: "memory"); }
__device__ __forceinline__ void cp_wait0()  { asm volatile("cp.async.wait_group 0;" ::: "memory"); }

// ---- bf16x3 path (GEMM1) ----
__device__ __forceinline__ void bf16_pack_split(float f0, float f1, uint32_t& hi, uint32_t& lo) {
    uint32_t h;
    asm("cvt.rn.bf16x2.f32 %0, %1, %2;" : "=r"(h) : "f"(f1), "f"(f0));  // hi-half=f1, lo-half=f0
    const float h0 = __uint_as_float(h << 16);
    const float h1 = __uint_as_float(h & 0xFFFF0000u);
    const float l0 = f0 - h0;
    const float l1 = f1 - h1;
    asm("cvt.rn.bf16x2.f32 %0, %1, %2;" : "=r"(lo) : "f"(l1), "f"(l0));
    hi = h;
}
__device__ __forceinline__ void mma_bf16(float* d, const uint32_t* a, const uint32_t* b) {
    asm volatile(
        "mma.sync.aligned.m16n8k16.row.col.f32.bf16.bf16.f32 "
        "{%0,%1,%2,%3}, {%4,%5,%6,%7}, {%8,%9}, {%0,%1,%2,%3};"
        : "+f"(d[0]), "+f"(d[1]), "+f"(d[2]), "+f"(d[3])
        : "r"(a[0]), "r"(a[1]), "r"(a[2]), "r"(a[3]), "r"(b[0]), "r"(b[1]));
}

// ---- fp16 2-pass path (GEMM2, GEMM3) ----
__device__ __forceinline__ uint32_t f16x2_of(float f0, float f1) {
    uint32_t r;
    asm("cvt.rn.f16x2.f32 %0, %1, %2;" : "=r"(r) : "f"(f1), "f"(f0));
    return r;
}
__device__ __forceinline__ void f16_pack_split(float f0, float f1, uint32_t& hi, uint32_t& lo) {
    asm("cvt.rn.f16x2.f32 %0, %1, %2;" : "=r"(hi) : "f"(f1), "f"(f0));
    float h0, h1;
    asm("{ .reg .b16 x,y; mov.b32 {x,y}, %2; cvt.f32.f16 %0, x; cvt.f32.f16 %1, y; }"
        : "=f"(h0), "=f"(h1) : "r"(hi));
    asm("cvt.rn.f16x2.f32 %0, %1, %2;" : "=r"(lo) : "f"(f1 - h1), "f"(f0 - h0));
}
__device__ __forceinline__ void mma_f16(float* d, const uint32_t* a, const uint32_t* b) {
    asm volatile(
        "mma.sync.aligned.m16n8k16.row.col.f32.f16.f16.f32 "
        "{%0,%1,%2,%3}, {%4,%5,%6,%7}, {%8,%9}, {%0,%1,%2,%3};"
        : "+f"(d[0]), "+f"(d[1]), "+f"(d[2]), "+f"(d[3])
        : "r"(a[0]), "r"(a[1]), "r"(a[2]), "r"(a[3]), "r"(b[0]), "r"(b[1]));
}

// ---------------- batched GEMM: C tile 128x128 = A[M,K] * B(k,n) ----------------
// Structure identical to the passing R14 kernel (cp.async double buffer, raw fp32
// SMEM, split/convert at fragment-load time).
// MODE 1: bf16x3 (3 passes)  — wq = x @ w_qs (K=1024) -> fp32 wq
// MODE 2: fp16x2 (2 passes)  — logits = wq@wq^T (K=256) -> fp32 attn
// MODE 3: fp16x2 (2 passes)  — e = attn @ x (K=512)    -> fp32 out
// fp16 scheme: A single-converted (ah), B hi/lo split (bh,bl): a*b ~= ah*bh + ah*bl.
template <int MODE>
__global__ __launch_bounds__(256, 2) void k_gemm(const float* __restrict__ Ain,
                                                 const float* __restrict__ Bin,
                                                 float* __restrict__ Cout) {
    constexpr int K   = (MODE == 1) ? TD : (MODE == 2) ? TH : TT;
    constexpr int NKB = K / 16;
    constexpr int LDA = K;
    constexpr int LDB = (MODE == 1) ? TH : (MODE == 2) ? TH : TD;
    constexpr int LDC = (MODE == 1) ? TH : (MODE == 2) ? TT : TD;
    constexpr bool BTR = (MODE == 2);          // B stored [n][k] in gmem
    constexpr bool F16 = (MODE != 1);          // fp16 2-pass vs bf16 3-pass
    constexpr int BR = BTR ? 128 : 16;
    constexpr int BC = BTR ? 24  : 132;

    __shared__ float sA[2][128][24];
    __shared__ float sB[2][BR][BC];

    const int tid = threadIdx.x, wid = tid >> 5, lane = tid & 31;
    const int wm = wid & 1, wn = wid >> 1;     // 2x4 warp grid, warp tile 64x32
    const int lr = lane >> 2, lq = lane & 3;
    const int z = blockIdx.z;
    const int m0 = blockIdx.y * 128;
    const int n0 = blockIdx.x * 128;

    size_t aoff, boff;
    if constexpr (MODE == 1) {
        aoff = (size_t)(z >> 4) * TT * TD;
        boff = (size_t)(z & 15) * TD * TH;
    } else if constexpr (MODE == 2) {
        aoff = (size_t)z * TT * TH;
        boff = aoff;
    } else {
        aoff = (size_t)z * TT * TT;
        boff = (size_t)(z >> 4) * TT * TD;
    }
    const float* pA_ = Ain + aoff + (size_t)m0 * LDA;
    const float* pB_ = BTR ? (Bin + boff + (size_t)n0 * LDB)   // [n][k] row offset
                           : (Bin + boff + n0);                // [k][n] col offset

    float acc[4][4][4];
#pragma unroll
    for (int mi = 0; mi < 4; mi++)
#pragma unroll
        for (int ni = 0; ni < 4; ni++)
#pragma unroll
            for (int e = 0; e < 4; e++) acc[mi][ni][e] = 0.0f;

    // ---- cp.async staging: one 16-wide K block per stage (R14-identical) ----
    auto issue_stage = [&](int kb, int s) {
#pragma unroll
        for (int i = 0; i < 2; i++) {
            const int cid = tid + i * 256;
            const int ar = cid >> 2, ac4 = cid & 3;
            cp16(smem_u32(&sA[s][ar][ac4 * 4]),
                 pA_ + (size_t)ar * LDA + kb * 16 + ac4 * 4);
            if constexpr (BTR) {
                const int nr = cid >> 2, kc4 = cid & 3;
                cp16(smem_u32(&sB[s][nr][kc4 * 4]),
                     pB_ + (size_t)nr * LDB + kb * 16 + kc4 * 4);
            } else {
                const int kr = cid >> 5, nc4 = cid & 31;
                cp16(smem_u32(&sB[s][kr][nc4 * 4]),
                     pB_ + (size_t)(kb * 16 + kr) * LDB + nc4 * 4);
            }
        }
        cp_commit();
    };

    issue_stage(0, 0);

#pragma unroll 1
    for (int kb = 0; kb < NKB; kb++) {
        const int s = kb & 1;
        cp_wait0();
        __syncthreads();
        if (kb + 1 < NKB) issue_stage(kb + 1, s ^ 1);   // copy overlaps MMAs below

        // ---- fragment load + convert/split in registers ----
        uint32_t ah[4][4], al[4][4], bh[4][2], bl[4][2];
#pragma unroll
        for (int mi = 0; mi < 4; mi++) {
            const int row = wm * 64 + mi * 16 + lr;
            const float2 v0 = *reinterpret_cast<const float2*>(&sA[s][row][2 * lq]);
            const float2 v1 = *reinterpret_cast<const float2*>(&sA[s][row + 8][2 * lq]);
            const float2 v2 = *reinterpret_cast<const float2*>(&sA[s][row][2 * lq + 8]);
            const float2 v3 = *reinterpret_cast<const float2*>(&sA[s][row + 8][2 * lq + 8]);
            if constexpr (F16) {
                ah[mi][0] = f16x2_of(v0.x, v0.y);
                ah[mi][1] = f16x2_of(v1.x, v1.y);
                ah[mi][2] = f16x2_of(v2.x, v2.y);
                ah[mi][3] = f16x2_of(v3.x, v3.y);
            } else {
                bf16_pack_split(v0.x, v0.y, ah[mi][0], al[mi][0]);
                bf16_pack_split(v1.x, v1.y, ah[mi][1], al[mi][1]);
                bf16_pack_split(v2.x, v2.y, ah[mi][2], al[mi][2]);
                bf16_pack_split(v3.x, v3.y, ah[mi][3], al[mi][3]);
            }
        }
#pragma unroll
        for (int ni = 0; ni < 4; ni++) {
            const int n = wn * 32 + ni * 8 + lr;
            float f0, f1, f2, f3;
            if constexpr (BTR) {
                const float2 u0 = *reinterpret_cast<const float2*>(&sB[s][n][2 * lq]);
                const float2 u1 = *reinterpret_cast<const float2*>(&sB[s][n][2 * lq + 8]);
                f0 = u0.x; f1 = u0.y; f2 = u1.x; f3 = u1.y;
            } else {
                f0 = sB[s][2 * lq][n];     f1 = sB[s][2 * lq + 1][n];
                f2 = sB[s][2 * lq + 8][n]; f3 = sB[s][2 * lq + 9][n];
            }
            if constexpr (F16) {
                f16_pack_split(f0, f1, bh[ni][0], bl[ni][0]);
                f16_pack_split(f2, f3, bh[ni][1], bl[ni][1]);
            } else {
                bf16_pack_split(f0, f1, bh[ni][0], bl[ni][0]);
                bf16_pack_split(f2, f3, bh[ni][1], bl[ni][1]);
            }
        }

        // ---- MMA passes (pass-major: dependent acc updates 16 MMAs apart) ----
        if constexpr (F16) {
#pragma unroll
            for (int mi = 0; mi < 4; mi++)
#pragma unroll
                for (int ni = 0; ni < 4; ni++)
                    mma_f16(acc[mi][ni], ah[mi], bh[ni]);    // a*bh
#pragma unroll
            for (int mi = 0; mi < 4; mi++)
#pragma unroll
                for (int ni = 0; ni < 4; ni++)
                    mma_f16(acc[mi][ni], ah[mi], bl[ni]);    // a*bl
        } else {
#pragma unroll
            for (int mi = 0; mi < 4; mi++)
#pragma unroll
                for (int ni = 0; ni < 4; ni++)
                    mma_bf16(acc[mi][ni], ah[mi], bh[ni]);   // hi*hi
#pragma unroll
            for (int mi = 0; mi < 4; mi++)
#pragma unroll
                for (int ni = 0; ni < 4; ni++)
                    mma_bf16(acc[mi][ni], ah[mi], bl[ni]);   // hi*lo
#pragma unroll
            for (int mi = 0; mi < 4; mi++)
#pragma unroll
                for (int ni = 0; ni < 4; ni++)
                    mma_bf16(acc[mi][ni], al[mi], bh[ni]);   // lo*hi
        }
    }

    // ---- epilogue: fp32 float2 stores (R14-identical) ----
    const int rbase = m0 + wm * 64 + lr;
    const int cbase = n0 + wn * 32 + lq * 2;
#pragma unroll
    for (int mi = 0; mi < 4; mi++)
#pragma unroll
        for (int ni = 0; ni < 4; ni++)
#pragma unroll
            for (int h = 0; h < 2; h++) {
                const int row = rbase + mi * 16 + h * 8;
                const int col = cbase + ni * 8;
                float* dst = Cout + (size_t)z * TT * LDC + (size_t)row * LDC + col;
                *reinterpret_cast<float2*>(dst) =
                    make_float2(acc[mi][ni][2 * h], acc[mi][ni][2 * h + 1]);
            }
}

// ---------------- softmax over rows of 512 (unchanged, passing) ----------------
__global__ __launch_bounds__(256) void k_softmax(float* __restrict__ attn) {
    __shared__ float redm[8];
    __shared__ float reds[8];
    float* p = attn + (size_t)blockIdx.x * TT;
    const int tid = threadIdx.x;

    float v0 = p[tid];
    float v1 = p[tid + 256];
    float m = fmaxf(v0, v1);
#pragma unroll
    for (int o = 16; o; o >>= 1) m = fmaxf(m, __shfl_xor_sync(0xffffffffu, m, o));
    if ((tid & 31) == 0) redm[tid >> 5] = m;
    __syncthreads();
    float mAll = redm[0];
#pragma unroll
    for (int w = 1; w < 8; w++) mAll = fmaxf(mAll, redm[w]);

    float e0 = expf(v0 - mAll);
    float e1 = expf(v1 - mAll);
    float s = e0 + e1;
#pragma unroll
    for (int o = 16; o; o >>= 1) s += __shfl_xor_sync(0xffffffffu, s, o);
    if ((tid & 31) == 0) reds[tid >> 5] = s;
    __syncthreads();
    float sAll = 0.0f;
#pragma unroll
    for (int w = 0; w < 8; w++) sAll += reds[w];
    const float inv = 1.0f / sAll;
    p[tid] = e0 * inv;
    p[tid + 256] = e1 * inv;
}

// ---------------- launcher (unchanged, passing) ----------------
extern "C" void kernel_launch(void* const* d_in, const int* in_sizes, int n_in,
                              void* d_out, int out_size) {
    (void)in_sizes; (void)n_in;
    const float* x   = (const float*)d_in[0];
    const float* wqs = (const float*)d_in[1];
    // d_in[2] = w_ks: unused in reference math (faithful to source bug)
    float* out = (float*)d_out;

    const long long EAGG = (long long)NBATCH * TT * TD;  // 33,554,432
    const long long ATTN = (long long)NBATCH * TT * TT;  // 16,777,216

    float* attn;
    if ((long long)out_size >= EAGG + ATTN) {
        attn = out + EAGG;
    } else {
        void* p = nullptr;
        cudaGetSymbolAddress(&p, g_attn_fb);
        attn = (float*)p;
    }
    void* wqp = nullptr;
    cudaGetSymbolAddress(&wqp, g_wq);
    float* wq = (float*)wqp;

    // GEMM1: wq = x @ w_qs            (bf16x3, high accuracy feeding the chain)
    k_gemm<1><<<dim3(TH / 128, TT / 128, NBATCH), 256>>>(x, wqs, wq);
    // GEMM2: logits = wq @ wq^T       (fp16x2)
    k_gemm<2><<<dim3(TT / 128, TT / 128, NBATCH), 256>>>(wq, wq, attn);
    // softmax in place
    k_softmax<<<NBATCH * TT, 256>>>(attn);
    // GEMM3: e = attn @ x             (fp16x2)
    k_gemm<3><<<dim3(TD / 128, TT / 128, NBATCH), 256>>>(attn, x, out);
}

// round 17
// speedup vs baseline: 1.5289x; 1.0710x over previous
#include <cuda_runtime.h>
#include <cstdint>

// Problem dims (fixed by reference setup_inputs)
#define TB 4      // batch
#define TT 512    // tokens
#define TD 1024   // d_model
#define TNC 16    // n_concepts
#define TH 256    // init_size
#define NBATCH (TB * TNC)   // 64 batched GEMMs

// ---------------- scratch (__device__ globals; allocation-free rule) ----------------
__device__ float g_wq[(size_t)NBATCH * TT * TH];      // fp32 wq[z][t][h]
__device__ float g_attn_fb[(size_t)NBATCH * TT * TT]; // fp32 attn if d_out has no slot

// ---------------- helpers ----------------
__device__ __forceinline__ uint32_t smem_u32(const void* p) {
    uint32_t a;
    asm("{ .reg .u64 t; cvta.to.shared.u64 t, %1; cvt.u32.u64 %0, t; }" : "=r"(a) : "l"(p));
    return a;
}
__device__ __forceinline__ void cp16(uint32_t dst, const void* src) {
    asm volatile("cp.async.cg.shared.global [%0], [%1], 16;" :: "r"(dst), "l"(src) : "memory");
}
__device__ __forceinline__ void cp_commit() { asm volatile("cp.async.commit_group;" ::: "memory"); }
__device__ __forceinline__ void cp_wait0()  { asm volatile("cp.async.wait_group 0;" ::: "memory"); }

// ---- fp16 helpers ----
__device__ __forceinline__ uint32_t f16x2_of(float f0, float f1) {
    uint32_t r;
    asm("cvt.rn.f16x2.f32 %0, %1, %2;" : "=r"(r) : "f"(f1), "f"(f0));
    return r;
}
// fp16 hi/lo split of a k-adjacent fp32 pair (lo half = even k)
__device__ __forceinline__ void f16_pack_split(float f0, float f1, uint32_t& hi, uint32_t& lo) {
    asm("cvt.rn.f16x2.f32 %0, %1, %2;" : "=r"(hi) : "f"(f1), "f"(f0));
    float h0, h1;
    asm("{ .reg .b16 x,y; mov.b32 {x,y}, %2; cvt.f32.f16 %0, x; cvt.f32.f16 %1, y; }"
        : "=f"(h0), "=f"(h1) : "r"(hi));
    asm("cvt.rn.f16x2.f32 %0, %1, %2;" : "=r"(lo) : "f"(f1 - h1), "f"(f0 - h0));
}
__device__ __forceinline__ void mma_f16(float* d, const uint32_t* a, const uint32_t* b) {
    asm volatile(
        "mma.sync.aligned.m16n8k16.row.col.f32.f16.f16.f32 "
        "{%0,%1,%2,%3}, {%4,%5,%6,%7}, {%8,%9}, {%0,%1,%2,%3};"
        : "+f"(d[0]), "+f"(d[1]), "+f"(d[2]), "+f"(d[3])
        : "r"(a[0]), "r"(a[1]), "r"(a[2]), "r"(a[3]), "r"(b[0]), "r"(b[1]));
}

// ---------------- fp16x2 batched GEMM: C tile 128x128 = A[M,K] * B(k,n) ----------------
// Structure identical to the passing R14/R16 kernels (cp.async double buffer, raw
// fp32 SMEM, convert/split at fragment-load time). All GEMMs use 2-pass fp16:
//   SPLITA (MODE 1): a*b ~= ah*bh + al*bh  (split A=x: O(1) values, residuals
//                    normal-range; B=w_qs single-converted, |w|~1e-3 normal)
//   SPLITB (MODE 2,3): a*b ~= ah*bh + ah*bl (A single, B split — proven R16)
template <int MODE>
__global__ __launch_bounds__(256, 2) void k_gemm(const float* __restrict__ Ain,
                                                 const float* __restrict__ Bin,
                                                 float* __restrict__ Cout) {
    constexpr int K   = (MODE == 1) ? TD : (MODE == 2) ? TH : TT;
    constexpr int NKB = K / 16;
    constexpr int LDA = K;
    constexpr int LDB = (MODE == 1) ? TH : (MODE == 2) ? TH : TD;
    constexpr int LDC = (MODE == 1) ? TH : (MODE == 2) ? TT : TD;
    constexpr bool BTR = (MODE == 2);          // B stored [n][k] in gmem
    constexpr bool SPLITA = (MODE == 1);       // split A instead of B
    constexpr int BR = BTR ? 128 : 16;
    constexpr int BC = BTR ? 24  : 132;

    __shared__ float sA[2][128][24];
    __shared__ float sB[2][BR][BC];

    const int tid = threadIdx.x, wid = tid >> 5, lane = tid & 31;
    const int wm = wid & 1, wn = wid >> 1;     // 2x4 warp grid, warp tile 64x32
    const int lr = lane >> 2, lq = lane & 3;
    const int z = blockIdx.z;
    const int m0 = blockIdx.y * 128;
    const int n0 = blockIdx.x * 128;

    size_t aoff, boff;
    if constexpr (MODE == 1) {
        aoff = (size_t)(z >> 4) * TT * TD;
        boff = (size_t)(z & 15) * TD * TH;
    } else if constexpr (MODE == 2) {
        aoff = (size_t)z * TT * TH;
        boff = aoff;
    } else {
        aoff = (size_t)z * TT * TT;
        boff = (size_t)(z >> 4) * TT * TD;
    }
    const float* pA_ = Ain + aoff + (size_t)m0 * LDA;
    const float* pB_ = BTR ? (Bin + boff + (size_t)n0 * LDB)   // [n][k] row offset
                           : (Bin + boff + n0);                // [k][n] col offset

    float acc[4][4][4];
#pragma unroll
    for (int mi = 0; mi < 4; mi++)
#pragma unroll
        for (int ni = 0; ni < 4; ni++)
#pragma unroll
            for (int e = 0; e < 4; e++) acc[mi][ni][e] = 0.0f;

    // ---- cp.async staging: one 16-wide K block per stage ----
    auto issue_stage = [&](int kb, int s) {
#pragma unroll
        for (int i = 0; i < 2; i++) {
            const int cid = tid + i * 256;
            const int ar = cid >> 2, ac4 = cid & 3;
            cp16(smem_u32(&sA[s][ar][ac4 * 4]),
                 pA_ + (size_t)ar * LDA + kb * 16 + ac4 * 4);
            if constexpr (BTR) {
                const int nr = cid >> 2, kc4 = cid & 3;
                cp16(smem_u32(&sB[s][nr][kc4 * 4]),
                     pB_ + (size_t)nr * LDB + kb * 16 + kc4 * 4);
            } else {
                const int kr = cid >> 5, nc4 = cid & 31;
                cp16(smem_u32(&sB[s][kr][nc4 * 4]),
                     pB_ + (size_t)(kb * 16 + kr) * LDB + nc4 * 4);
            }
        }
        cp_commit();
    };

    issue_stage(0, 0);

#pragma unroll 1
    for (int kb = 0; kb < NKB; kb++) {
        const int s = kb & 1;
        cp_wait0();
        __syncthreads();
        if (kb + 1 < NKB) issue_stage(kb + 1, s ^ 1);   // copy overlaps MMAs below

        // ---- fragment load + convert/split in registers ----
        uint32_t ah[4][4], al[4][4], bh[4][2], bl[4][2];
#pragma unroll
        for (int mi = 0; mi < 4; mi++) {
            const int row = wm * 64 + mi * 16 + lr;
            const float2 v0 = *reinterpret_cast<const float2*>(&sA[s][row][2 * lq]);
            const float2 v1 = *reinterpret_cast<const float2*>(&sA[s][row + 8][2 * lq]);
            const float2 v2 = *reinterpret_cast<const float2*>(&sA[s][row][2 * lq + 8]);
            const float2 v3 = *reinterpret_cast<const float2*>(&sA[s][row + 8][2 * lq + 8]);
            if constexpr (SPLITA) {
                f16_pack_split(v0.x, v0.y, ah[mi][0], al[mi][0]);
                f16_pack_split(v1.x, v1.y, ah[mi][1], al[mi][1]);
                f16_pack_split(v2.x, v2.y, ah[mi][2], al[mi][2]);
                f16_pack_split(v3.x, v3.y, ah[mi][3], al[mi][3]);
            } else {
                ah[mi][0] = f16x2_of(v0.x, v0.y);
                ah[mi][1] = f16x2_of(v1.x, v1.y);
                ah[mi][2] = f16x2_of(v2.x, v2.y);
                ah[mi][3] = f16x2_of(v3.x, v3.y);
            }
        }
#pragma unroll
        for (int ni = 0; ni < 4; ni++) {
            const int n = wn * 32 + ni * 8 + lr;
            float f0, f1, f2, f3;
            if constexpr (BTR) {
                const float2 u0 = *reinterpret_cast<const float2*>(&sB[s][n][2 * lq]);
                const float2 u1 = *reinterpret_cast<const float2*>(&sB[s][n][2 * lq + 8]);
                f0 = u0.x; f1 = u0.y; f2 = u1.x; f3 = u1.y;
            } else {
                f0 = sB[s][2 * lq][n];     f1 = sB[s][2 * lq + 1][n];
                f2 = sB[s][2 * lq + 8][n]; f3 = sB[s][2 * lq + 9][n];
            }
            if constexpr (SPLITA) {
                bh[ni][0] = f16x2_of(f0, f1);
                bh[ni][1] = f16x2_of(f2, f3);
            } else {
                f16_pack_split(f0, f1, bh[ni][0], bl[ni][0]);
                f16_pack_split(f2, f3, bh[ni][1], bl[ni][1]);
            }
        }

        // ---- 2 MMA passes (pass-major: dependent acc updates 16 MMAs apart) ----
#pragma unroll
        for (int mi = 0; mi < 4; mi++)
#pragma unroll
            for (int ni = 0; ni < 4; ni++)
                mma_f16(acc[mi][ni], ah[mi], bh[ni]);        // ah*bh
        if constexpr (SPLITA) {
#pragma unroll
            for (int mi = 0; mi < 4; mi++)
#pragma unroll
                for (int ni = 0; ni < 4; ni++)
                    mma_f16(acc[mi][ni], al[mi], bh[ni]);    // al*bh
        } else {
#pragma unroll
            for (int mi = 0; mi < 4; mi++)
#pragma unroll
                for (int ni = 0; ni < 4; ni++)
                    mma_f16(acc[mi][ni], ah[mi], bl[ni]);    // ah*bl
        }
    }

    // ---- epilogue: fp32 float2 stores (R14/R16-identical) ----
    const int rbase = m0 + wm * 64 + lr;
    const int cbase = n0 + wn * 32 + lq * 2;
#pragma unroll
    for (int mi = 0; mi < 4; mi++)
#pragma unroll
        for (int ni = 0; ni < 4; ni++)
#pragma unroll
            for (int h = 0; h < 2; h++) {
                const int row = rbase + mi * 16 + h * 8;
                const int col = cbase + ni * 8;
                float* dst = Cout + (size_t)z * TT * LDC + (size_t)row * LDC + col;
                *reinterpret_cast<float2*>(dst) =
                    make_float2(acc[mi][ni][2 * h], acc[mi][ni][2 * h + 1]);
            }
}

// ---------------- softmax over rows of 512 (unchanged, passing) ----------------
__global__ __launch_bounds__(256) void k_softmax(float* __restrict__ attn) {
    __shared__ float redm[8];
    __shared__ float reds[8];
    float* p = attn + (size_t)blockIdx.x * TT;
    const int tid = threadIdx.x;

    float v0 = p[tid];
    float v1 = p[tid + 256];
    float m = fmaxf(v0, v1);
#pragma unroll
    for (int o = 16; o; o >>= 1) m = fmaxf(m, __shfl_xor_sync(0xffffffffu, m, o));
    if ((tid & 31) == 0) redm[tid >> 5] = m;
    __syncthreads();
    float mAll = redm[0];
#pragma unroll
    for (int w = 1; w < 8; w++) mAll = fmaxf(mAll, redm[w]);

    float e0 = expf(v0 - mAll);
    float e1 = expf(v1 - mAll);
    float s = e0 + e1;
#pragma unroll
    for (int o = 16; o; o >>= 1) s += __shfl_xor_sync(0xffffffffu, s, o);
    if ((tid & 31) == 0) reds[tid >> 5] = s;
    __syncthreads();
    float sAll = 0.0f;
#pragma unroll
    for (int w = 0; w < 8; w++) sAll += reds[w];
    const float inv = 1.0f / sAll;
    p[tid] = e0 * inv;
    p[tid + 256] = e1 * inv;
}

// ---------------- launcher (unchanged, passing) ----------------
extern "C" void kernel_launch(void* const* d_in, const int* in_sizes, int n_in,
                              void* d_out, int out_size) {
    (void)in_sizes; (void)n_in;
    const float* x   = (const float*)d_in[0];
    const float* wqs = (const float*)d_in[1];
    // d_in[2] = w_ks: unused in reference math (faithful to source bug)
    float* out = (float*)d_out;

    const long long EAGG = (long long)NBATCH * TT * TD;  // 33,554,432
    const long long ATTN = (long long)NBATCH * TT * TT;  // 16,777,216

    float* attn;
    if ((long long)out_size >= EAGG + ATTN) {
        attn = out + EAGG;
    } else {
        void* p = nullptr;
        cudaGetSymbolAddress(&p, g_attn_fb);
        attn = (float*)p;
    }
    void* wqp = nullptr;
    cudaGetSymbolAddress(&wqp, g_wq);
    float* wq = (float*)wqp;

    // GEMM1: wq = x @ w_qs            (fp16x2, split-A)
    k_gemm<1><<<dim3(TH / 128, TT / 128, NBATCH), 256>>>(x, wqs, wq);
    // GEMM2: logits = wq @ wq^T       (fp16x2, split-B)
    k_gemm<2><<<dim3(TT / 128, TT / 128, NBATCH), 256>>>(wq, wq, attn);
    // softmax in place
    k_softmax<<<NBATCH * TT, 256>>>(attn);
    // GEMM3: e = attn @ x             (fp16x2, split-B)
    k_gemm<3><<<dim3(TD / 128, TT / 128, NBATCH), 256>>>(attn, x, out);
}